// round 4
// baseline (speedup 1.0000x reference)
#include <cuda_runtime.h>
#include <math.h>

typedef unsigned long long ull;

#define NBC    6          // B*C
#define NLEV   6
#define NSTAT  9          // S1 S2 S3 S4 S5 Sm1 Sm2 T2(log2-weighted) count
#define NTILE  64         // 32^3 tiles per 128^3 volume
#define NBLK   (NBC * NTILE)

// Per-block partials for levels 0..4 (45 doubles each) + level-5 map values.
__device__ double g_part[NBLK][45];
__device__ float  g_l5map[NBLK];   // [bc*64 + tile] = 32^3 tile sum (level-5 cell)

// ---- packed f32x2 helpers (Blackwell 2xFP32; ptxas won't auto-emit) ----
__device__ __forceinline__ ull pk2(float lo, float hi) {
    ull r; asm("mov.b64 %0, {%1, %2};" : "=l"(r) : "f"(lo), "f"(hi)); return r;
}
__device__ __forceinline__ float2 upk2(ull v) {
    float2 f; asm("mov.b64 {%0, %1}, %2;" : "=f"(f.x), "=f"(f.y) : "l"(v)); return f;
}
__device__ __forceinline__ ull add2(ull a, ull b) {
    ull r; asm("add.rn.f32x2 %0, %1, %2;" : "=l"(r) : "l"(a), "l"(b)); return r;
}
__device__ __forceinline__ ull mul2(ull a, ull b) {
    ull r; asm("mul.rn.f32x2 %0, %1, %2;" : "=l"(r) : "l"(a), "l"(b)); return r;
}
__device__ __forceinline__ ull fma2(ull a, ull b, ull c) {
    ull r; asm("fma.rn.f32x2 %0, %1, %2, %3;" : "=l"(r) : "l"(a), "l"(b), "l"(c)); return r;
}
__device__ __forceinline__ float rcpa(float x) {
    float r; asm("rcp.approx.f32 %0, %1;" : "=f"(r) : "f"(x)); return r;
}
__device__ __forceinline__ float lg2a(float x) {
    float r; asm("lg2.approx.f32 %0, %1;" : "=f"(r) : "f"(x)); return r;
}

// Packed stat accumulation for 2 nonzero voxels.
__device__ __forceinline__ void acc_pair(ull x, ull& S1, ull& S2, ull& S3, ull& S4,
                                         ull& S5, ull& Sm1, ull& Sm2, ull& T2) {
    float2 f = upk2(x);
    ull inv = pk2(rcpa(f.x), rcpa(f.y));    // 2x MUFU.RCP
    ull lg  = pk2(lg2a(f.x), lg2a(f.y));    // 2x MUFU.LG2
    S1 = add2(S1, x);
    ull xx = mul2(x, x);
    S2 = add2(S2, xx);
    ull x3 = mul2(xx, x);
    S3 = add2(S3, x3);
    S4 = fma2(xx, xx, S4);
    S5 = fma2(x3, xx, S5);
    Sm1 = add2(Sm1, inv);
    Sm2 = fma2(inv, inv, Sm2);
    T2  = fma2(x, lg, T2);
}

// Scalar stat accumulation (zero-skipping) into a 9-float array.
__device__ __forceinline__ void acc_scalar(float v, float* st) {
    if (v != 0.0f) {
        float inv = rcpa(v), lg = lg2a(v);
        float v2 = v * v, v3 = v2 * v;
        st[0] += v;
        st[1] += v2;
        st[2] += v3;
        st[3] += v2 * v2;
        st[4] += v3 * v2;
        st[5] += inv;
        st[6] += inv * inv;
        st[7] += v * lg;
        st[8] += 1.0f;
    }
}

__device__ __forceinline__ float wred32(float v) {
#pragma unroll
    for (int o = 16; o; o >>= 1) v += __shfl_down_sync(0xFFFFFFFFu, v, o);
    return v;
}

// ONE fused pass: grid (64 tiles, 6 bc), 512 threads. Each thread owns a 4^3
// subcube of the 32^3 tile: level0 stats on 64 voxels, level1 stats on its 8
// octant sums, one level2 value. Smem pooling: level3 (64 thr), level4 (8 thr),
// level5 value (tile sum) to global. Block partials (45 doubles) -> g_part.
__global__ void __launch_bounds__(512, 2) fused_pyramid_kernel(const float* __restrict__ img) {
    const int tile = blockIdx.x;                 // 0..63
    const int bc   = blockIdx.y;                 // 0..5
    const int tid  = threadIdx.x;

    const int tw = tile & 3, th = (tile >> 2) & 3, td = tile >> 4;
    const int sw = tid & 7,  sh = (tid >> 3) & 7, sd = tid >> 6;

    const int d0 = td * 32 + sd * 4;
    const int h0 = th * 32 + sh * 4;
    const int w0 = tw * 32 + sw * 4;

    const float* p = img + ((size_t)bc << 21) + ((size_t)d0 << 14) + (h0 << 7) + w0;

    // Level-0 packed accumulators + count
    ull S1 = 0, S2 = 0, S3 = 0, S4 = 0, S5 = 0, Sm1 = 0, Sm2 = 0, T2 = 0;
    float cnt0 = 0.0f;
    // Level-1 scalar stats, level-2 value
    float st1[9];
#pragma unroll
    for (int j = 0; j < 9; j++) st1[j] = 0.0f;
    float l2v = 0.0f;

#pragma unroll
    for (int cd = 0; cd < 2; cd++) {
#pragma unroll
        for (int ch = 0; ch < 2; ch++) {
            const float* q = p + (cd << 15) + (ch << 8);   // (2*cd)<<14, (2*ch)<<7
            float4 rA = *reinterpret_cast<const float4*>(q);
            float4 rB = *reinterpret_cast<const float4*>(q + 128);      // h+1
            float4 rC = *reinterpret_cast<const float4*>(q + 16384);    // d+1
            float4 rD = *reinterpret_cast<const float4*>(q + 16512);    // d+1,h+1

            float mn = fminf(
                fminf(fminf(fminf(rA.x, rA.y), fminf(rA.z, rA.w)),
                      fminf(fminf(rB.x, rB.y), fminf(rB.z, rB.w))),
                fminf(fminf(fminf(rC.x, rC.y), fminf(rC.z, rC.w)),
                      fminf(fminf(rD.x, rD.y), fminf(rD.z, rD.w))));

            // octant sums (cw = 0 uses .x/.y, cw = 1 uses .z/.w)
            float l1a = (rA.x + rA.y) + (rB.x + rB.y) + (rC.x + rC.y) + (rD.x + rD.y);
            float l1b = (rA.z + rA.w) + (rB.z + rB.w) + (rC.z + rC.w) + (rD.z + rD.w);

            if (mn != 0.0f) {
                acc_pair(pk2(rA.x, rA.y), S1, S2, S3, S4, S5, Sm1, Sm2, T2);
                acc_pair(pk2(rA.z, rA.w), S1, S2, S3, S4, S5, Sm1, Sm2, T2);
                acc_pair(pk2(rB.x, rB.y), S1, S2, S3, S4, S5, Sm1, Sm2, T2);
                acc_pair(pk2(rB.z, rB.w), S1, S2, S3, S4, S5, Sm1, Sm2, T2);
                acc_pair(pk2(rC.x, rC.y), S1, S2, S3, S4, S5, Sm1, Sm2, T2);
                acc_pair(pk2(rC.z, rC.w), S1, S2, S3, S4, S5, Sm1, Sm2, T2);
                acc_pair(pk2(rD.x, rD.y), S1, S2, S3, S4, S5, Sm1, Sm2, T2);
                acc_pair(pk2(rD.z, rD.w), S1, S2, S3, S4, S5, Sm1, Sm2, T2);
                cnt0 += 16.0f;
            } else {
                // rare: exact zeros present — scalar zero-skipping into the
                // same packed accumulators (hi lane padded with 0 contributions)
                float vals[16] = {rA.x, rA.y, rA.z, rA.w, rB.x, rB.y, rB.z, rB.w,
                                  rC.x, rC.y, rC.z, rC.w, rD.x, rD.y, rD.z, rD.w};
#pragma unroll 4
                for (int j = 0; j < 16; j++) {
                    float v = vals[j];
                    if (v != 0.0f) {
                        float inv = rcpa(v), lg = lg2a(v);
                        float v2 = v * v, v3 = v2 * v;
                        S1 = add2(S1, pk2(v, 0.f));
                        S2 = add2(S2, pk2(v2, 0.f));
                        S3 = add2(S3, pk2(v3, 0.f));
                        S4 = add2(S4, pk2(v2 * v2, 0.f));
                        S5 = add2(S5, pk2(v3 * v2, 0.f));
                        Sm1 = add2(Sm1, pk2(inv, 0.f));
                        Sm2 = add2(Sm2, pk2(inv * inv, 0.f));
                        T2 = add2(T2, pk2(v * lg, 0.f));
                        cnt0 += 1.0f;
                    }
                }
            }
            acc_scalar(l1a, st1);
            acc_scalar(l1b, st1);
            l2v += l1a + l1b;
        }
    }

    // Level-2 stats (one value per thread)
    float st2[9];
#pragma unroll
    for (int j = 0; j < 9; j++) st2[j] = 0.0f;
    acc_scalar(l2v, st2);

    // ---------- shared-memory pooling + block reduction ----------
    __shared__ float  l2s[512];
    __shared__ float  l3s[64];
    __shared__ double sacc[45];

    if (tid < 45) sacc[tid] = 0.0;
    l2s[tid] = l2v;
    __syncthreads();

    float st3[9];
    float l3v = 0.0f;
    if (tid < 64) {
#pragma unroll
        for (int j = 0; j < 9; j++) st3[j] = 0.0f;
        int jd = tid >> 4, jh = (tid >> 2) & 3, jw = tid & 3;
        int b3 = (jd << 7) + (jh << 4) + (jw << 1);   // (2jd)<<6 + (2jh)<<3 + 2jw
#pragma unroll
        for (int di = 0; di < 2; di++)
#pragma unroll
            for (int hi = 0; hi < 2; hi++)
#pragma unroll
                for (int wi = 0; wi < 2; wi++)
                    l3v += l2s[b3 + (di << 6) + (hi << 3) + wi];
        acc_scalar(l3v, st3);
        l3s[tid] = l3v;
    }

    // warp-reduce L0/L1/L2 (27 floats) and smem-atomic into sacc
    {
        float2 f;
        float st0[9];
        f = upk2(S1);  st0[0] = f.x + f.y;
        f = upk2(S2);  st0[1] = f.x + f.y;
        f = upk2(S3);  st0[2] = f.x + f.y;
        f = upk2(S4);  st0[3] = f.x + f.y;
        f = upk2(S5);  st0[4] = f.x + f.y;
        f = upk2(Sm1); st0[5] = f.x + f.y;
        f = upk2(Sm2); st0[6] = f.x + f.y;
        f = upk2(T2);  st0[7] = f.x + f.y;
        st0[8] = cnt0;
        int lane = tid & 31;
#pragma unroll
        for (int j = 0; j < 9; j++) {
            float a0 = wred32(st0[j]);
            float a1 = wred32(st1[j]);
            float a2 = wred32(st2[j]);
            if (lane == 0) {
                atomicAdd(&sacc[j],      (double)a0);
                atomicAdd(&sacc[9 + j],  (double)a1);
                atomicAdd(&sacc[18 + j], (double)a2);
            }
        }
        if (tid < 64) {   // warps 0,1 fully active
#pragma unroll
            for (int j = 0; j < 9; j++) {
                float a3 = wred32(st3[j]);
                if (lane == 0) atomicAdd(&sacc[27 + j], (double)a3);
            }
        }
    }
    __syncthreads();

    if (tid < 8) {
        int md = (tid >> 2) & 1, mh = (tid >> 1) & 1, mw = tid & 1;
        int b4 = (md << 5) + (mh << 3) + (mw << 1);   // (2md)<<4 + (2mh)<<2 + 2mw
        float l4v = 0.0f;
#pragma unroll
        for (int di = 0; di < 2; di++)
#pragma unroll
            for (int hi = 0; hi < 2; hi++)
#pragma unroll
                for (int wi = 0; wi < 2; wi++)
                    l4v += l3s[b4 + (di << 4) + (hi << 2) + wi];
        float st4[9];
#pragma unroll
        for (int j = 0; j < 9; j++) st4[j] = 0.0f;
        acc_scalar(l4v, st4);
        float l5p = l4v;
#pragma unroll
        for (int o = 4; o; o >>= 1) {
            l5p += __shfl_down_sync(0xFFu, l5p, o);
#pragma unroll
            for (int j = 0; j < 9; j++) st4[j] += __shfl_down_sync(0xFFu, st4[j], o);
        }
        if (tid == 0) {
#pragma unroll
            for (int j = 0; j < 9; j++) atomicAdd(&sacc[36 + j], (double)st4[j]);
            g_l5map[bc * 64 + tile] = l5p;   // level-5 cell value (tile sum)
        }
    }
    __syncthreads();

    if (tid < 45) g_part[bc * 64 + tile][tid] = sacc[tid];
}

// Finalize: one block. Reduce partials over 64 tiles per (bc, level<=4, stat),
// build level-5 stats from the 64 tile sums per bc, then compute the 48 slopes.
__global__ void finalize_kernel(const int* __restrict__ bounds, float* __restrict__ out) {
    __shared__ double acc[NBC][NLEV][NSTAT];
    int tid = threadIdx.x;

    if (tid < 270) {                       // levels 0..4
        int bc = tid / 45, rem = tid % 45;
        int level = rem / 9, stat = rem % 9;
        double s = 0.0;
#pragma unroll 4
        for (int t = 0; t < 64; t++) s += g_part[bc * 64 + t][level * 9 + stat];
        acc[bc][level][stat] = s;
    } else if (tid < 276) {                // level 5: 64 values per bc
        int bc = tid - 270;
        double s[9] = {0, 0, 0, 0, 0, 0, 0, 0, 0};
        for (int t = 0; t < 64; t++) {
            double v = (double)g_l5map[bc * 64 + t];
            if (v != 0.0) {
                double v2 = v * v, v3 = v2 * v;
                s[0] += v; s[1] += v2; s[2] += v3;
                s[3] += v2 * v2; s[4] += v3 * v2;
                double inv = 1.0 / v;
                s[5] += inv; s[6] += inv * inv;
                s[7] += v * log2(v); s[8] += 1.0;
            }
        }
#pragma unroll
        for (int j = 0; j < 9; j++) acc[bc][5][j] = s[j];
    }
    __syncthreads();

    if (tid >= NBC * 8) return;
    int bc = tid >> 3;
    int k  = bounds[tid & 7];

    double b   = acc[bc][0][0];            // total image sum per (b,c)
    double lnb = log(b);

    double sp = 0.0, spq = 0.0;
    for (int s = 0; s < NLEV; s++) {
        const double* a = acc[bc][s];
        double p;
        if (k == 1) {
            p = (a[7] * M_LN2) / b - lnb;          // sum x*ln(x)/b - ln b
        } else if (k == 0) {
            p = log(a[8]);                          // log(nonzero count)
        } else {
            double S;
            switch (k) {
                case  2: S = a[1]; break;
                case  3: S = a[2]; break;
                case  4: S = a[3]; break;
                case  5: S = a[4]; break;
                case -1: S = a[5]; break;
                case -2: S = a[6]; break;
                default: S = nan(""); break;
            }
            p = log(S) - (double)k * lnb;           // log(sum (x/b)^k)
        }
        sp  += p;
        spq += p * ((double)s * M_LN2);
    }
    const double qs  = 15.0 * M_LN2;
    const double q2s = 55.0 * M_LN2 * M_LN2;
    const double den = 6.0 * q2s - qs * qs;
    double aa = (k == 1) ? 1.0 : 1.0 / (double)(k - 1);
    out[tid] = (float)(aa * (6.0 * spq - sp * qs) / den);
}

extern "C" void kernel_launch(void* const* d_in, const int* in_sizes, int n_in,
                              void* d_out, int out_size) {
    const float* img    = (const float*)d_in[0];
    const int*   bounds = (const int*)d_in[1];
    float*       out    = (float*)d_out;

    fused_pyramid_kernel<<<dim3(NTILE, NBC), 512>>>(img);
    finalize_kernel<<<1, 512>>>(bounds, out);
}

// round 5
// speedup vs baseline: 3.8011x; 3.8011x over previous
#include <cuda_runtime.h>
#include <math.h>

typedef unsigned long long ull;

#define NBC    6          // B*C
#define NLEV   6
#define NSTAT  9          // S1 S2 S3 S4 S5 Sm1 Sm2 T2(x*log2 x) count
#define GXA    256        // kernel A grid.x (per bc) -> 262144/(256*256)=4 exact iters
#define NTILB  8          // kernel B tiles per bc (2x2x2 of 32^3 L1-cells)

// L1 map (64^3 per bc) + per-block stat partials. Static __device__: allocation-free.
__device__ float  g_l1[NBC * 64 * 64 * 64];
__device__ double g_partA[NBC][GXA][NSTAT];          // level-0 partials
__device__ double g_partB[NBC][NTILB][5 * NSTAT];    // levels 1..5 partials

// ---- packed f32x2 helpers (Blackwell 2xFP32; ptxas won't auto-emit) ----
__device__ __forceinline__ ull pk2(float lo, float hi) {
    ull r; asm("mov.b64 %0, {%1, %2};" : "=l"(r) : "f"(lo), "f"(hi)); return r;
}
__device__ __forceinline__ float2 upk2(ull v) {
    float2 f; asm("mov.b64 {%0, %1}, %2;" : "=f"(f.x), "=f"(f.y) : "l"(v)); return f;
}
__device__ __forceinline__ ull add2(ull a, ull b) {
    ull r; asm("add.rn.f32x2 %0, %1, %2;" : "=l"(r) : "l"(a), "l"(b)); return r;
}
__device__ __forceinline__ ull mul2(ull a, ull b) {
    ull r; asm("mul.rn.f32x2 %0, %1, %2;" : "=l"(r) : "l"(a), "l"(b)); return r;
}
__device__ __forceinline__ ull fma2(ull a, ull b, ull c) {
    ull r; asm("fma.rn.f32x2 %0, %1, %2, %3;" : "=l"(r) : "l"(a), "l"(b), "l"(c)); return r;
}
__device__ __forceinline__ float rcpa(float x) {
    float r; asm("rcp.approx.f32 %0, %1;" : "=f"(r) : "f"(x)); return r;
}
__device__ __forceinline__ float lg2a(float x) {
    float r; asm("lg2.approx.f32 %0, %1;" : "=f"(r) : "f"(x)); return r;
}

// Packed stat accumulation for 2 nonzero values.
__device__ __forceinline__ void acc_pair(ull x, ull& S1, ull& S2, ull& S3, ull& S4,
                                         ull& S5, ull& Sm1, ull& Sm2, ull& T2) {
    float2 f = upk2(x);
    ull inv = pk2(rcpa(f.x), rcpa(f.y));    // 2x MUFU.RCP
    ull lg  = pk2(lg2a(f.x), lg2a(f.y));    // 2x MUFU.LG2
    S1 = add2(S1, x);
    ull xx = mul2(x, x);
    S2 = add2(S2, xx);
    ull x3 = mul2(xx, x);
    S3 = add2(S3, x3);
    S4 = fma2(xx, xx, S4);
    S5 = fma2(x3, xx, S5);
    Sm1 = add2(Sm1, inv);
    Sm2 = fma2(inv, inv, Sm2);
    T2  = fma2(x, lg, T2);
}

// Scalar stat accumulation (zero-skipping) into packed accumulators (lo lane).
__device__ __forceinline__ void acc_one(float v, ull& S1, ull& S2, ull& S3, ull& S4,
                                        ull& S5, ull& Sm1, ull& Sm2, ull& T2, float& cnt) {
    if (v != 0.0f) {
        float inv = rcpa(v), lg = lg2a(v);
        float v2 = v * v, v3 = v2 * v;
        S1 = add2(S1, pk2(v, 0.f));
        S2 = add2(S2, pk2(v2, 0.f));
        S3 = add2(S3, pk2(v3, 0.f));
        S4 = add2(S4, pk2(v2 * v2, 0.f));
        S5 = add2(S5, pk2(v3 * v2, 0.f));
        Sm1 = add2(Sm1, pk2(inv, 0.f));
        Sm2 = add2(Sm2, pk2(inv * inv, 0.f));
        T2 = add2(T2, pk2(v * lg, 0.f));
        cnt += 1.0f;
    }
}

// Scalar stat accumulation (zero-skipping) into a 9-float array.
__device__ __forceinline__ void acc_scalar(float v, float* st) {
    if (v != 0.0f) {
        float inv = rcpa(v), lg = lg2a(v);
        float v2 = v * v, v3 = v2 * v;
        st[0] += v;  st[1] += v2;  st[2] += v3;
        st[3] += v2 * v2;  st[4] += v3 * v2;
        st[5] += inv;  st[6] += inv * inv;
        st[7] += v * lg;  st[8] += 1.0f;
    }
}

__device__ __forceinline__ float wred32(float v) {
#pragma unroll
    for (int o = 16; o; o >>= 1) v += __shfl_down_sync(0xFFFFFFFFu, v, o);
    return v;
}

// -------- Kernel A: level-0 stats + write L1 map. Flat grid-stride, balanced. --------
// grid (GXA, 6), 256 threads; each thread does exactly 4 L1 cells (8 voxels each).
__global__ void __launch_bounds__(256) l0_kernel(const float* __restrict__ img) {
    const int bc = blockIdx.y;
    const float* __restrict__ inp = img + ((size_t)bc << 21);
    float* __restrict__ outp = g_l1 + ((size_t)bc << 18);

    ull S1 = 0, S2 = 0, S3 = 0, S4 = 0, S5 = 0, Sm1 = 0, Sm2 = 0, T2 = 0;
    float cnt0 = 0.0f;

    const int stride = GXA * 256;                        // 65536
    int idx = blockIdx.x * 256 + threadIdx.x;
#pragma unroll
    for (int it = 0; it < 4; it++, idx += stride) {      // 262144 / 65536 = 4 exact
        int ow = idx & 63, oh = (idx >> 6) & 63, od = idx >> 12;
        int base = (od << 15) + (oh << 8) + (ow << 1);

        float2 v0 = *reinterpret_cast<const float2*>(inp + base);
        float2 v1 = *reinterpret_cast<const float2*>(inp + base + 128);
        float2 v2 = *reinterpret_cast<const float2*>(inp + base + 16384);
        float2 v3 = *reinterpret_cast<const float2*>(inp + base + 16512);

        float mn = fminf(fminf(fminf(v0.x, v0.y), fminf(v1.x, v1.y)),
                         fminf(fminf(v2.x, v2.y), fminf(v3.x, v3.y)));
        float psum;
        if (mn != 0.0f) {
            acc_pair(pk2(v0.x, v0.y), S1, S2, S3, S4, S5, Sm1, Sm2, T2);
            acc_pair(pk2(v1.x, v1.y), S1, S2, S3, S4, S5, Sm1, Sm2, T2);
            acc_pair(pk2(v2.x, v2.y), S1, S2, S3, S4, S5, Sm1, Sm2, T2);
            acc_pair(pk2(v3.x, v3.y), S1, S2, S3, S4, S5, Sm1, Sm2, T2);
            cnt0 += 8.0f;
            psum = (v0.x + v0.y) + (v1.x + v1.y) + (v2.x + v2.y) + (v3.x + v3.y);
        } else {
            float vals[8] = {v0.x, v0.y, v1.x, v1.y, v2.x, v2.y, v3.x, v3.y};
            psum = 0.0f;
#pragma unroll
            for (int j = 0; j < 8; j++) {
                psum += vals[j];
                acc_one(vals[j], S1, S2, S3, S4, S5, Sm1, Sm2, T2, cnt0);
            }
        }
        outp[idx] = psum;
    }

    // block reduce 9 stats -> g_partA[bc][blockIdx.x]
    float st0[9];
    {
        float2 f;
        f = upk2(S1);  st0[0] = f.x + f.y;
        f = upk2(S2);  st0[1] = f.x + f.y;
        f = upk2(S3);  st0[2] = f.x + f.y;
        f = upk2(S4);  st0[3] = f.x + f.y;
        f = upk2(S5);  st0[4] = f.x + f.y;
        f = upk2(Sm1); st0[5] = f.x + f.y;
        f = upk2(Sm2); st0[6] = f.x + f.y;
        f = upk2(T2);  st0[7] = f.x + f.y;
        st0[8] = cnt0;
    }
    __shared__ double sm[8][9];
    int lane = threadIdx.x & 31, warp = threadIdx.x >> 5;
#pragma unroll
    for (int j = 0; j < 9; j++) {
        float a = wred32(st0[j]);
        if (lane == 0) sm[warp][j] = (double)a;
    }
    __syncthreads();
    if (threadIdx.x < 9) {
        double s = 0.0;
#pragma unroll
        for (int w = 0; w < 8; w++) s += sm[w][threadIdx.x];
        g_partA[bc][blockIdx.x][threadIdx.x] = s;
    }
}

// -------- Kernel B: levels 1..5 from the L1 map. grid (8, 6), 512 threads. --------
// Thread owns a 4^3 cube of L1 cells: L1 stats (64), L2 stats (8 octants), one L3
// value. Smem pooling: L4 (64 thr), L5 (8 thr). 45 partials per block.
__global__ void __launch_bounds__(512) pyr_kernel() {
    const int tile = blockIdx.x;                  // 0..7 (2x2x2 of 32^3 L1-cubes)
    const int bc   = blockIdx.y;
    const int tid  = threadIdx.x;

    const int tw = tile & 1, th = (tile >> 1) & 1, td = tile >> 2;
    const int sw = tid & 7,  sh = (tid >> 3) & 7, sd = tid >> 6;

    const int d0 = td * 32 + sd * 4;
    const int h0 = th * 32 + sh * 4;
    const int w0 = tw * 32 + sw * 4;

    const float* __restrict__ p = g_l1 + ((size_t)bc << 18) + (d0 << 12) + (h0 << 6) + w0;

    ull S1 = 0, S2 = 0, S3 = 0, S4 = 0, S5 = 0, Sm1 = 0, Sm2 = 0, T2 = 0;
    float cnt1 = 0.0f;
    float st2[9];
#pragma unroll
    for (int j = 0; j < 9; j++) st2[j] = 0.0f;
    float l3v = 0.0f;

#pragma unroll
    for (int cd = 0; cd < 2; cd++) {
#pragma unroll
        for (int ch = 0; ch < 2; ch++) {
            const float* q = p + (cd << 13) + (ch << 7);    // (2cd)<<12, (2ch)<<6
            float4 rA = *reinterpret_cast<const float4*>(q);
            float4 rB = *reinterpret_cast<const float4*>(q + 64);     // h+1
            float4 rC = *reinterpret_cast<const float4*>(q + 4096);   // d+1
            float4 rD = *reinterpret_cast<const float4*>(q + 4160);   // d+1,h+1

            float mn = fminf(
                fminf(fminf(fminf(rA.x, rA.y), fminf(rA.z, rA.w)),
                      fminf(fminf(rB.x, rB.y), fminf(rB.z, rB.w))),
                fminf(fminf(fminf(rC.x, rC.y), fminf(rC.z, rC.w)),
                      fminf(fminf(rD.x, rD.y), fminf(rD.z, rD.w))));

            float l2a = (rA.x + rA.y) + (rB.x + rB.y) + (rC.x + rC.y) + (rD.x + rD.y);
            float l2b = (rA.z + rA.w) + (rB.z + rB.w) + (rC.z + rC.w) + (rD.z + rD.w);

            if (mn != 0.0f) {
                acc_pair(pk2(rA.x, rA.y), S1, S2, S3, S4, S5, Sm1, Sm2, T2);
                acc_pair(pk2(rA.z, rA.w), S1, S2, S3, S4, S5, Sm1, Sm2, T2);
                acc_pair(pk2(rB.x, rB.y), S1, S2, S3, S4, S5, Sm1, Sm2, T2);
                acc_pair(pk2(rB.z, rB.w), S1, S2, S3, S4, S5, Sm1, Sm2, T2);
                acc_pair(pk2(rC.x, rC.y), S1, S2, S3, S4, S5, Sm1, Sm2, T2);
                acc_pair(pk2(rC.z, rC.w), S1, S2, S3, S4, S5, Sm1, Sm2, T2);
                acc_pair(pk2(rD.x, rD.y), S1, S2, S3, S4, S5, Sm1, Sm2, T2);
                acc_pair(pk2(rD.z, rD.w), S1, S2, S3, S4, S5, Sm1, Sm2, T2);
                cnt1 += 16.0f;
            } else {
                float vals[16] = {rA.x, rA.y, rA.z, rA.w, rB.x, rB.y, rB.z, rB.w,
                                  rC.x, rC.y, rC.z, rC.w, rD.x, rD.y, rD.z, rD.w};
#pragma unroll 4
                for (int j = 0; j < 16; j++)
                    acc_one(vals[j], S1, S2, S3, S4, S5, Sm1, Sm2, T2, cnt1);
            }
            acc_scalar(l2a, st2);
            acc_scalar(l2b, st2);
            l3v += l2a + l2b;
        }
    }

    float st3[9];
#pragma unroll
    for (int j = 0; j < 9; j++) st3[j] = 0.0f;
    acc_scalar(l3v, st3);

    __shared__ float  l3s[512];
    __shared__ float  l4s[64];
    __shared__ double sacc[45];

    if (tid < 45) sacc[tid] = 0.0;
    l3s[tid] = l3v;
    __syncthreads();

    float st4[9];
    float l4v = 0.0f;
    if (tid < 64) {
#pragma unroll
        for (int j = 0; j < 9; j++) st4[j] = 0.0f;
        int jd = tid >> 4, jh = (tid >> 2) & 3, jw = tid & 3;
        int b4 = (jd << 7) + (jh << 4) + (jw << 1);
#pragma unroll
        for (int di = 0; di < 2; di++)
#pragma unroll
            for (int hi = 0; hi < 2; hi++)
#pragma unroll
                for (int wi = 0; wi < 2; wi++)
                    l4v += l3s[b4 + (di << 6) + (hi << 3) + wi];
        acc_scalar(l4v, st4);
        l4s[tid] = l4v;
    }

    // warp-reduce L1/L2/L3 and smem-atomic into sacc
    {
        float2 f;
        float st1[9];
        f = upk2(S1);  st1[0] = f.x + f.y;
        f = upk2(S2);  st1[1] = f.x + f.y;
        f = upk2(S3);  st1[2] = f.x + f.y;
        f = upk2(S4);  st1[3] = f.x + f.y;
        f = upk2(S5);  st1[4] = f.x + f.y;
        f = upk2(Sm1); st1[5] = f.x + f.y;
        f = upk2(Sm2); st1[6] = f.x + f.y;
        f = upk2(T2);  st1[7] = f.x + f.y;
        st1[8] = cnt1;
        int lane = tid & 31;
#pragma unroll
        for (int j = 0; j < 9; j++) {
            float a1 = wred32(st1[j]);
            float a2 = wred32(st2[j]);
            float a3 = wred32(st3[j]);
            if (lane == 0) {
                atomicAdd(&sacc[j],      (double)a1);
                atomicAdd(&sacc[9 + j],  (double)a2);
                atomicAdd(&sacc[18 + j], (double)a3);
            }
        }
        if (tid < 64) {
#pragma unroll
            for (int j = 0; j < 9; j++) {
                float a4 = wred32(st4[j]);
                if (lane == 0) atomicAdd(&sacc[27 + j], (double)a4);
            }
        }
    }
    __syncthreads();

    if (tid < 8) {
        int md = (tid >> 2) & 1, mh = (tid >> 1) & 1, mw = tid & 1;
        int b5 = (md << 5) + (mh << 3) + (mw << 1);
        float l5v = 0.0f;
#pragma unroll
        for (int di = 0; di < 2; di++)
#pragma unroll
            for (int hi = 0; hi < 2; hi++)
#pragma unroll
                for (int wi = 0; wi < 2; wi++)
                    l5v += l4s[b5 + (di << 4) + (hi << 2) + wi];
        float st5[9];
#pragma unroll
        for (int j = 0; j < 9; j++) st5[j] = 0.0f;
        acc_scalar(l5v, st5);
#pragma unroll
        for (int o = 4; o; o >>= 1)
#pragma unroll
            for (int j = 0; j < 9; j++) st5[j] += __shfl_down_sync(0xFFu, st5[j], o);
        if (tid == 0) {
#pragma unroll
            for (int j = 0; j < 9; j++) sacc[36 + j] += (double)st5[j];
        }
    }
    __syncthreads();

    if (tid < 45) g_partB[bc][tile][tid] = sacc[tid];
}

// -------- Finalize: reduce partials + 48 slopes, all-float transcendentals. --------
__global__ void finalize_kernel(const int* __restrict__ bounds, float* __restrict__ out) {
    __shared__ double red[54][8];
    __shared__ float  acc[NBC][NLEV][NSTAT];
    int tid = threadIdx.x;

    // level-0: 54 (bc,stat) pairs x 8 partial-summers over GXA blocks
    if (tid < 432) {
        int g = tid >> 3, part = tid & 7;
        int bc = g / 9, stat = g % 9;
        double s = 0.0;
        for (int t = part; t < GXA; t += 8) s += g_partA[bc][t][stat];
        red[g][part] = s;
    }
    __syncthreads();
    if (tid < 54) {
        double s = 0.0;
#pragma unroll
        for (int p = 0; p < 8; p++) s += red[tid][p];
        acc[tid / 9][0][tid % 9] = (float)s;
    }
    // levels 1..5: 270 (bc,level,stat) triples, 8 tiles each
    if (tid >= 64 && tid < 64 + 270) {
        int u = tid - 64;
        int bc = u / 45, r = u % 45;
        double s = 0.0;
#pragma unroll
        for (int t = 0; t < NTILB; t++) s += g_partB[bc][t][r];
        acc[bc][1 + r / 9][r % 9] = (float)s;
    }
    __syncthreads();

    if (tid >= NBC * 8) return;
    int bc = tid >> 3;
    int k  = bounds[tid & 7];

    const float LN2 = 0.69314718055994531f;
    float b   = acc[bc][0][0];             // total image sum per (b,c)
    float lnb = logf(b);

    float sp = 0.0f, spq = 0.0f;
    for (int s = 0; s < NLEV; s++) {
        const float* a = acc[bc][s];
        float p;
        if (k == 1) {
            p = (a[7] * LN2) / b - lnb;            // sum x*ln x / b - ln b
        } else if (k == 0) {
            p = logf(a[8]);                         // log(nonzero count)
        } else {
            float S;
            switch (k) {
                case  2: S = a[1]; break;
                case  3: S = a[2]; break;
                case  4: S = a[3]; break;
                case  5: S = a[4]; break;
                case -1: S = a[5]; break;
                case -2: S = a[6]; break;
                default: S = __int_as_float(0x7FC00000); break;
            }
            p = logf(S) - (float)k * lnb;           // log(sum (x/b)^k)
        }
        sp  += p;
        spq += p * ((float)s * LN2);
    }
    const float qs  = 15.0f * LN2;
    const float q2s = 55.0f * LN2 * LN2;
    const float den = 6.0f * q2s - qs * qs;
    float aa = (k == 1) ? 1.0f : 1.0f / (float)(k - 1);
    out[tid] = aa * (6.0f * spq - sp * qs) / den;
}

extern "C" void kernel_launch(void* const* d_in, const int* in_sizes, int n_in,
                              void* d_out, int out_size) {
    const float* img    = (const float*)d_in[0];
    const int*   bounds = (const int*)d_in[1];
    float*       out    = (float*)d_out;

    l0_kernel<<<dim3(GXA, NBC), 256>>>(img);    // level-0 stats + L1 map (balanced)
    pyr_kernel<<<dim3(NTILB, NBC), 512>>>();    // levels 1..5 from L1 map
    finalize_kernel<<<1, 512>>>(bounds, out);
}

// round 6
// speedup vs baseline: 4.1075x; 1.0806x over previous
#include <cuda_runtime.h>
#include <math.h>

typedef unsigned long long ull;

#define NBC    6          // B*C
#define NLEV   6
#define NSTAT  9          // S1 S2 S3 S4 S5 Sm1 Sm2 T2(x*log2 x) count
#define GXA    256        // l0 grid.x per bc -> 262144/(256*256)=4 exact iters
#define NTILB  8          // pyr tiles per bc (2x2x2 of 32^3 L1-cells)

// Static __device__ scratch (allocation-free).
__device__ float        g_l1[NBC * 64 * 64 * 64];      // level-1 map (64^3 per bc)
__device__ double       g_partA[NBC][GXA][NSTAT];      // level-0 per-block partials
__device__ double       g_partB[NBC][NTILB][54];       // [0..44]=levels1-5, [45..53]=level0 slice
__device__ unsigned int g_ctr;                         // last-block counter (reset by l0)

// ---- packed f32x2 helpers (Blackwell 2xFP32; ptxas won't auto-emit) ----
__device__ __forceinline__ ull pk2(float lo, float hi) {
    ull r; asm("mov.b64 %0, {%1, %2};" : "=l"(r) : "f"(lo), "f"(hi)); return r;
}
__device__ __forceinline__ float2 upk2(ull v) {
    float2 f; asm("mov.b64 {%0, %1}, %2;" : "=f"(f.x), "=f"(f.y) : "l"(v)); return f;
}
__device__ __forceinline__ ull add2(ull a, ull b) {
    ull r; asm("add.rn.f32x2 %0, %1, %2;" : "=l"(r) : "l"(a), "l"(b)); return r;
}
__device__ __forceinline__ ull mul2(ull a, ull b) {
    ull r; asm("mul.rn.f32x2 %0, %1, %2;" : "=l"(r) : "l"(a), "l"(b)); return r;
}
__device__ __forceinline__ ull fma2(ull a, ull b, ull c) {
    ull r; asm("fma.rn.f32x2 %0, %1, %2, %3;" : "=l"(r) : "l"(a), "l"(b), "l"(c)); return r;
}
__device__ __forceinline__ float rcpa(float x) {
    float r; asm("rcp.approx.f32 %0, %1;" : "=f"(r) : "f"(x)); return r;
}
__device__ __forceinline__ float lg2a(float x) {
    float r; asm("lg2.approx.f32 %0, %1;" : "=f"(r) : "f"(x)); return r;
}

// Packed stat accumulation for 2 nonzero values.
__device__ __forceinline__ void acc_pair(ull x, ull& S1, ull& S2, ull& S3, ull& S4,
                                         ull& S5, ull& Sm1, ull& Sm2, ull& T2) {
    float2 f = upk2(x);
    ull inv = pk2(rcpa(f.x), rcpa(f.y));    // 2x MUFU.RCP
    ull lg  = pk2(lg2a(f.x), lg2a(f.y));    // 2x MUFU.LG2
    S1 = add2(S1, x);
    ull xx = mul2(x, x);
    S2 = add2(S2, xx);
    ull x3 = mul2(xx, x);
    S3 = add2(S3, x3);
    S4 = fma2(xx, xx, S4);
    S5 = fma2(x3, xx, S5);
    Sm1 = add2(Sm1, inv);
    Sm2 = fma2(inv, inv, Sm2);
    T2  = fma2(x, lg, T2);
}

// Scalar zero-skipping accumulation into packed accumulators (lo lane).
__device__ __forceinline__ void acc_one(float v, ull& S1, ull& S2, ull& S3, ull& S4,
                                        ull& S5, ull& Sm1, ull& Sm2, ull& T2, float& cnt) {
    if (v != 0.0f) {
        float inv = rcpa(v), lg = lg2a(v);
        float v2 = v * v, v3 = v2 * v;
        S1 = add2(S1, pk2(v, 0.f));
        S2 = add2(S2, pk2(v2, 0.f));
        S3 = add2(S3, pk2(v3, 0.f));
        S4 = add2(S4, pk2(v2 * v2, 0.f));
        S5 = add2(S5, pk2(v3 * v2, 0.f));
        Sm1 = add2(Sm1, pk2(inv, 0.f));
        Sm2 = add2(Sm2, pk2(inv * inv, 0.f));
        T2 = add2(T2, pk2(v * lg, 0.f));
        cnt += 1.0f;
    }
}

// Scalar zero-skipping accumulation into a 9-float array.
__device__ __forceinline__ void acc_scalar(float v, float* st) {
    if (v != 0.0f) {
        float inv = rcpa(v), lg = lg2a(v);
        float v2 = v * v, v3 = v2 * v;
        st[0] += v;  st[1] += v2;  st[2] += v3;
        st[3] += v2 * v2;  st[4] += v3 * v2;
        st[5] += inv;  st[6] += inv * inv;
        st[7] += v * lg;  st[8] += 1.0f;
    }
}

__device__ __forceinline__ float wred32(float v) {
#pragma unroll
    for (int o = 16; o; o >>= 1) v += __shfl_down_sync(0xFFFFFFFFu, v, o);
    return v;
}

// Process one 2x2x2 octant given its 4 packed float2 loads. Returns pooled sum.
__device__ __forceinline__ float do_octant(ull q0, ull q1, ull q2, ull q3,
                                           ull& S1, ull& S2, ull& S3, ull& S4,
                                           ull& S5, ull& Sm1, ull& Sm2, ull& T2,
                                           float& cnt) {
    // pooled sum (packed)
    ull ps = add2(add2(q0, q1), add2(q2, q3));
    float2 pf = upk2(ps);
    float psum = pf.x + pf.y;
    // zero test: product of all 8 (underflow -> safe fallback to slow path)
    ull pr = mul2(mul2(q0, q1), mul2(q2, q3));
    float2 prf = upk2(pr);
    if (prf.x * prf.y != 0.0f) {
        acc_pair(q0, S1, S2, S3, S4, S5, Sm1, Sm2, T2);
        acc_pair(q1, S1, S2, S3, S4, S5, Sm1, Sm2, T2);
        acc_pair(q2, S1, S2, S3, S4, S5, Sm1, Sm2, T2);
        acc_pair(q3, S1, S2, S3, S4, S5, Sm1, Sm2, T2);
        cnt += 8.0f;
    } else {
        float2 a = upk2(q0), b = upk2(q1), c = upk2(q2), d = upk2(q3);
        float vals[8] = {a.x, a.y, b.x, b.y, c.x, c.y, d.x, d.y};
#pragma unroll
        for (int j = 0; j < 8; j++)
            acc_one(vals[j], S1, S2, S3, S4, S5, Sm1, Sm2, T2, cnt);
    }
    return psum;
}

// -------- Kernel A: level-0 stats + write L1 map. grid (GXA, 6), 256 thr. --------
__global__ void __launch_bounds__(256) l0_kernel(const float* __restrict__ img) {
    if ((blockIdx.x | blockIdx.y | threadIdx.x) == 0) g_ctr = 0;   // reset for pyr

    const int bc = blockIdx.y;
    const float* __restrict__ inp = img + ((size_t)bc << 21);
    float* __restrict__ outp = g_l1 + ((size_t)bc << 18);

    ull S1 = 0, S2 = 0, S3 = 0, S4 = 0, S5 = 0, Sm1 = 0, Sm2 = 0, T2 = 0;
    float cnt0 = 0.0f;

    const int stride = GXA * 256;                        // 65536
    const int idx0 = blockIdx.x * 256 + threadIdx.x;

#pragma unroll
    for (int g = 0; g < 2; g++) {                        // 2 groups x 2 iterations
        ull v[8];
        int idxs[2];
#pragma unroll
        for (int it = 0; it < 2; it++) {                 // front-batch 8 loads (MLP=8)
            int idx = idx0 + (g * 2 + it) * stride;
            idxs[it] = idx;
            int ow = idx & 63, oh = (idx >> 6) & 63, od = idx >> 12;
            int base = (od << 15) + (oh << 8) + (ow << 1);
            v[it * 4 + 0] = *reinterpret_cast<const ull*>(inp + base);
            v[it * 4 + 1] = *reinterpret_cast<const ull*>(inp + base + 128);
            v[it * 4 + 2] = *reinterpret_cast<const ull*>(inp + base + 16384);
            v[it * 4 + 3] = *reinterpret_cast<const ull*>(inp + base + 16512);
        }
#pragma unroll
        for (int it = 0; it < 2; it++) {
            float psum = do_octant(v[it * 4], v[it * 4 + 1], v[it * 4 + 2], v[it * 4 + 3],
                                   S1, S2, S3, S4, S5, Sm1, Sm2, T2, cnt0);
            outp[idxs[it]] = psum;
        }
    }

    // block reduce 9 stats -> g_partA[bc][blockIdx.x]
    float st0[9];
    {
        float2 f;
        f = upk2(S1);  st0[0] = f.x + f.y;
        f = upk2(S2);  st0[1] = f.x + f.y;
        f = upk2(S3);  st0[2] = f.x + f.y;
        f = upk2(S4);  st0[3] = f.x + f.y;
        f = upk2(S5);  st0[4] = f.x + f.y;
        f = upk2(Sm1); st0[5] = f.x + f.y;
        f = upk2(Sm2); st0[6] = f.x + f.y;
        f = upk2(T2);  st0[7] = f.x + f.y;
        st0[8] = cnt0;
    }
    __shared__ double sm[8][9];
    int lane = threadIdx.x & 31, warp = threadIdx.x >> 5;
#pragma unroll
    for (int j = 0; j < 9; j++) {
        float a = wred32(st0[j]);
        if (lane == 0) sm[warp][j] = (double)a;
    }
    __syncthreads();
    if (threadIdx.x < 9) {
        double s = 0.0;
#pragma unroll
        for (int w = 0; w < 8; w++) s += sm[w][threadIdx.x];
        g_partA[bc][blockIdx.x][threadIdx.x] = s;
    }
}

// -------- Kernel B: levels 1..5 + level-0 partial fold + last-block finalize. --------
// grid (8, 6), 512 threads. Thread owns 4^3 L1 cells.
__global__ void __launch_bounds__(512) pyr_kernel(const int* __restrict__ bounds,
                                                  float* __restrict__ out) {
    const int tile = blockIdx.x;                  // 0..7
    const int bc   = blockIdx.y;
    const int tid  = threadIdx.x;

    __shared__ float  l3s[512];
    __shared__ float  l4s[64];
    __shared__ double sacc[54];
    __shared__ double redA[9][32];

    // prefetch this block's 32-row slice of level-0 partials
    if (tid < 288) redA[tid >> 5][tid & 31] = g_partA[bc][(tile << 5) + (tid & 31)][tid >> 5];

    const int tw = tile & 1, th = (tile >> 1) & 1, td = tile >> 2;
    const int sw = tid & 7,  sh = (tid >> 3) & 7, sd = tid >> 6;
    const int d0 = td * 32 + sd * 4;
    const int h0 = th * 32 + sh * 4;
    const int w0 = tw * 32 + sw * 4;

    const float* __restrict__ p = g_l1 + ((size_t)bc << 18) + (d0 << 12) + (h0 << 6) + w0;

    ull S1 = 0, S2 = 0, S3 = 0, S4 = 0, S5 = 0, Sm1 = 0, Sm2 = 0, T2 = 0;
    float cnt1 = 0.0f;
    float st2[9];
#pragma unroll
    for (int j = 0; j < 9; j++) st2[j] = 0.0f;
    float l3v = 0.0f;

#pragma unroll
    for (int cd = 0; cd < 2; cd++) {
#pragma unroll
        for (int ch = 0; ch < 2; ch++) {
            const float* q = p + (cd << 13) + (ch << 7);
            ull qA0 = *reinterpret_cast<const ull*>(q);
            ull qA1 = *reinterpret_cast<const ull*>(q + 2);
            ull qB0 = *reinterpret_cast<const ull*>(q + 64);
            ull qB1 = *reinterpret_cast<const ull*>(q + 66);
            ull qC0 = *reinterpret_cast<const ull*>(q + 4096);
            ull qC1 = *reinterpret_cast<const ull*>(q + 4098);
            ull qD0 = *reinterpret_cast<const ull*>(q + 4160);
            ull qD1 = *reinterpret_cast<const ull*>(q + 4162);

            float l2a = do_octant(qA0, qB0, qC0, qD0,
                                  S1, S2, S3, S4, S5, Sm1, Sm2, T2, cnt1);
            float l2b = do_octant(qA1, qB1, qC1, qD1,
                                  S1, S2, S3, S4, S5, Sm1, Sm2, T2, cnt1);
            acc_scalar(l2a, st2);
            acc_scalar(l2b, st2);
            l3v += l2a + l2b;
        }
    }

    float st3[9];
#pragma unroll
    for (int j = 0; j < 9; j++) st3[j] = 0.0f;
    acc_scalar(l3v, st3);

    if (tid < 54) sacc[tid] = 0.0;
    l3s[tid] = l3v;
    __syncthreads();

    float st4[9];
    float l4v = 0.0f;
    if (tid < 64) {
#pragma unroll
        for (int j = 0; j < 9; j++) st4[j] = 0.0f;
        int jd = tid >> 4, jh = (tid >> 2) & 3, jw = tid & 3;
        int b4 = (jd << 7) + (jh << 4) + (jw << 1);
#pragma unroll
        for (int di = 0; di < 2; di++)
#pragma unroll
            for (int hi = 0; hi < 2; hi++)
#pragma unroll
                for (int wi = 0; wi < 2; wi++)
                    l4v += l3s[b4 + (di << 6) + (hi << 3) + wi];
        acc_scalar(l4v, st4);
        l4s[tid] = l4v;
    }

    // fold level-0 slice (warp 4, lanes 0..8)
    if (tid >= 128 && tid < 137) {
        double s = 0.0;
#pragma unroll
        for (int r = 0; r < 32; r++) s += redA[tid - 128][r];
        sacc[45 + (tid - 128)] = s;
    }

    // warp-reduce L1/L2/L3 + smem atomics
    {
        float2 f;
        float st1[9];
        f = upk2(S1);  st1[0] = f.x + f.y;
        f = upk2(S2);  st1[1] = f.x + f.y;
        f = upk2(S3);  st1[2] = f.x + f.y;
        f = upk2(S4);  st1[3] = f.x + f.y;
        f = upk2(S5);  st1[4] = f.x + f.y;
        f = upk2(Sm1); st1[5] = f.x + f.y;
        f = upk2(Sm2); st1[6] = f.x + f.y;
        f = upk2(T2);  st1[7] = f.x + f.y;
        st1[8] = cnt1;
        int lane = tid & 31;
#pragma unroll
        for (int j = 0; j < 9; j++) {
            float a1 = wred32(st1[j]);
            float a2 = wred32(st2[j]);
            float a3 = wred32(st3[j]);
            if (lane == 0) {
                atomicAdd(&sacc[j],      (double)a1);
                atomicAdd(&sacc[9 + j],  (double)a2);
                atomicAdd(&sacc[18 + j], (double)a3);
            }
        }
        if (tid < 64) {
#pragma unroll
            for (int j = 0; j < 9; j++) {
                float a4 = wred32(st4[j]);
                if (lane == 0) atomicAdd(&sacc[27 + j], (double)a4);
            }
        }
    }
    __syncthreads();

    if (tid < 8) {
        int md = (tid >> 2) & 1, mh = (tid >> 1) & 1, mw = tid & 1;
        int b5 = (md << 5) + (mh << 3) + (mw << 1);
        float l5v = 0.0f;
#pragma unroll
        for (int di = 0; di < 2; di++)
#pragma unroll
            for (int hi = 0; hi < 2; hi++)
#pragma unroll
                for (int wi = 0; wi < 2; wi++)
                    l5v += l4s[b5 + (di << 4) + (hi << 2) + wi];
        float st5[9];
#pragma unroll
        for (int j = 0; j < 9; j++) st5[j] = 0.0f;
        acc_scalar(l5v, st5);
#pragma unroll
        for (int o = 4; o; o >>= 1)
#pragma unroll
            for (int j = 0; j < 9; j++) st5[j] += __shfl_down_sync(0xFFu, st5[j], o);
        if (tid == 0) {
#pragma unroll
            for (int j = 0; j < 9; j++) sacc[36 + j] += (double)st5[j];
        }
    }
    __syncthreads();

    if (tid < 54) g_partB[bc][tile][tid] = sacc[tid];

    // ---------- last-block finalize ----------
    __threadfence();
    __shared__ unsigned int isLast;
    if (tid == 0) isLast = (atomicAdd(&g_ctr, 1) == NTILB * NBC - 1) ? 1u : 0u;
    __syncthreads();
    if (!isLast) return;
    __threadfence();

    __shared__ float acc[NBC][NLEV][NSTAT];
    if (tid < NBC * 54) {
        int abc = tid / 54, j = tid % 54;
        double s = 0.0;
#pragma unroll
        for (int t = 0; t < NTILB; t++) s += g_partB[abc][t][j];
        int level = (j < 45) ? (1 + j / 9) : 0;
        int stat  = (j < 45) ? (j % 9) : (j - 45);
        acc[abc][level][stat] = (float)s;
    }
    __syncthreads();

    if (tid >= NBC * 8) return;
    int obc = tid >> 3;
    int k   = bounds[tid & 7];

    const float LN2 = 0.69314718055994531f;
    float b   = acc[obc][0][0];
    float lnb = logf(b);

    float sp = 0.0f, spq = 0.0f;
    for (int s = 0; s < NLEV; s++) {
        const float* a = acc[obc][s];
        float pv;
        if (k == 1) {
            pv = (a[7] * LN2) / b - lnb;
        } else if (k == 0) {
            pv = logf(a[8]);
        } else {
            float S;
            switch (k) {
                case  2: S = a[1]; break;
                case  3: S = a[2]; break;
                case  4: S = a[3]; break;
                case  5: S = a[4]; break;
                case -1: S = a[5]; break;
                case -2: S = a[6]; break;
                default: S = __int_as_float(0x7FC00000); break;
            }
            pv = logf(S) - (float)k * lnb;
        }
        sp  += pv;
        spq += pv * ((float)s * LN2);
    }
    const float qs  = 15.0f * LN2;
    const float q2s = 55.0f * LN2 * LN2;
    const float den = 6.0f * q2s - qs * qs;
    float aa = (k == 1) ? 1.0f : 1.0f / (float)(k - 1);
    out[tid] = aa * (6.0f * spq - sp * qs) / den;
}

extern "C" void kernel_launch(void* const* d_in, const int* in_sizes, int n_in,
                              void* d_out, int out_size) {
    const float* img    = (const float*)d_in[0];
    const int*   bounds = (const int*)d_in[1];
    float*       out    = (float*)d_out;

    l0_kernel<<<dim3(GXA, NBC), 256>>>(img);              // level-0 stats + L1 map
    pyr_kernel<<<dim3(NTILB, NBC), 512>>>(bounds, out);   // levels 1..5 + finalize
}